// round 17
// baseline (speedup 1.0000x reference)
#include <cuda_runtime.h>
#include <cuda_fp16.h>
#include <cstdint>

#define CC   3
#define OO   8
#define HH   128
#define WW   128
#define HO   124
#define WO   124
#define P25  25

#define ROWSPAN 21                // 6 overlapping row-tiles: 0,21,42,63,84,103
#define XT_W  36                  // 32 + 4 halo (even)
#define XT_H  25                  // 21 + 4 halo

typedef unsigned long long ull;

__device__ __forceinline__ unsigned h2_as_u32(__half2 h)
{
    unsigned u;
    asm("mov.b32 %0, %1;" : "=r"(u) : "r"(*(unsigned*)&h));
    return *(unsigned*)&h;
}
__device__ __forceinline__ __half2 u32_as_h2(unsigned u)
{
    return *(__half2*)&u;
}

// One output row from the 5-slot ring (slot = xrow % 5), phase J = row % 5.
// w[p] = (x, -x) half2; kp[p] = (-K_hit, +K_miss) half2.
// min over both halves of (w + kp) yields (hit, -miss).
template<int J>
__device__ __forceinline__ float row_compute(const __half2* __restrict__ w,
                                             const __half2* __restrict__ kp)
{
    __half2 cu[5];
#pragma unroll
    for (int u = 0; u < 5; ++u) {
        const int s = ((J + u) % 5) * 5;
        __half2 acc = __hadd2(w[s], kp[u * 5]);
#pragma unroll
        for (int v = 1; v < 5; ++v)
            acc = __hmin2(acc, __hadd2(w[s + v], kp[u * 5 + v]));
        cu[u] = acc;
    }
    const __half2 r = __hmin2(__hmin2(__hmin2(cu[0], cu[1]),
                                      __hmin2(cu[2], cu[3])), cu[4]);
    return __low2float(r) + __high2float(r);   // hit - miss
}

// Load the 5 taps of x row (R+4) as 2 LDS.64 + 1 LDS.32 from the parity-
// aligned base, into ring slot (R+4)%5; compute row R; store statically.
#define ROW_STEP(R)                                                              \
    do {                                                                         \
        const char* bp = (const char*)(base + ((R) + 4) * XT_W);                 \
        const int sl = (((R) + 4) % 5) * 5;                                      \
        *(ull*)&w[sl]     = *(const ull*)(bp);                                   \
        *(ull*)&w[sl + 2] = *(const ull*)(bp + 8);                               \
        w[sl + 4]         = *(const __half2*)(bp + 16);                          \
        op[(R) * WO] = row_compute<(R) % 5>(w, kp);                              \
    } while (0)

__global__ __launch_bounds__(256, 4)
void mnn_kernel(const float* __restrict__ x,
                const float* __restrict__ kh_g,
                const float* __restrict__ km_g,
                float* __restrict__ out)
{
    __shared__ __half2 sxA[XT_H * XT_W];   // A[j] = (x,-x)(j)
    __shared__ __half2 sxB[XT_H * XT_W];   // B[j] = (x,-x)(j+1)  (B[last] unused)
    __shared__ __half2 wsm[OO * P25];      // (-kh, +km) for all 8 o, this c

    const int tx  = threadIdx.x;           // 0..31 column
    const int o   = threadIdx.y;           // 0..7  output channel
    const int tid = o * 32 + tx;

    // Overlapping tiles both axes -> all store lanes in-range; overlap cells
    // rewritten with identical values (deterministic). Even column origins
    // keep the float2 staging loads 8-byte aligned.
    static const int WO0[4] = {0, 30, 62, 92};
    const int wo0 = WO0[blockIdx.x];
    const int ho0 = (blockIdx.y == 5) ? 103 : blockIdx.y * ROWSPAN;
    const int bc  = blockIdx.z;             // b*CC + c
    const int b   = bc / CC;
    const int c   = bc % CC;

    // ---- cooperative weight staging: 1 LDG pair per thread (tid < 200) ----
    if (tid < OO * P25) {
        const int oo = tid / P25;
        const int p  = tid % P25;
        const float kh = __ldg(kh_g + (oo * CC + c) * P25 + p);
        const float km = __ldg(km_g + (oo * CC + c) * P25 + p);
        wsm[tid] = __halves2half2(__float2half_rn(-kh), __float2half_rn(km));
    }

    // ---- x tile staged via float2; (x,-x) = splat-cvt + sign XOR ----
    const float* __restrict__ xb = x + (size_t)bc * HH * WW;
    for (int i = tid; i < (XT_H * XT_W) / 2; i += 256) {     // 450 pairs
        const int e   = 2 * i;
        const int rr  = e / XT_W;
        const int cc2 = e % XT_W;                            // even
        const float2 v2 = *(const float2*)(xb + (ho0 + rr) * WW + wo0 + cc2);
        const __half2 h0 = u32_as_h2(h2_as_u32(__float2half2_rn(v2.x)) ^ 0x80000000u);
        const __half2 h1 = u32_as_h2(h2_as_u32(__float2half2_rn(v2.y)) ^ 0x80000000u);
        sxA[e]     = h0;                                     // (x, -x)
        sxA[e + 1] = h1;
        if (e) sxB[e - 1] = h0;                              // B[j] = A[j+1]
        sxB[e] = h1;
    }
    __syncthreads();

    // ---- per-thread weights from smem (warp-uniform broadcast LDS) ----
    __half2 kp[P25];
    {
        const __half2* __restrict__ wp = &wsm[o * P25];
#pragma unroll
        for (int p = 0; p < P25; ++p) kp[p] = wp[p];
    }

    // Parity-aligned base: even tx -> A + tx (even index);
    // odd tx -> B + tx - 1 (even index); both give taps orig[tx..tx+4].
    const __half2* base = (tx & 1) ? (sxB + tx - 1) : (sxA + tx);

    // ---- ring prologue: x rows 0..3 into slots 0..3 (3 LDS each) ----
    __half2 w[P25];
#pragma unroll
    for (int i = 0; i < 4; ++i) {
        const char* bp = (const char*)(base + i * XT_W);
        *(ull*)&w[i * 5]     = *(const ull*)(bp);
        *(ull*)&w[i * 5 + 2] = *(const ull*)(bp + 8);
        w[i * 5 + 4]         = *(const __half2*)(bp + 16);
    }

    float* __restrict__ op =
        out + ((size_t)(b * OO * CC + o * CC + c) * HO + ho0) * WO + wo0 + tx;

    // ---- 21 output rows, fully unrolled, all offsets static ----
    ROW_STEP(0);  ROW_STEP(1);  ROW_STEP(2);  ROW_STEP(3);  ROW_STEP(4);
    ROW_STEP(5);  ROW_STEP(6);  ROW_STEP(7);  ROW_STEP(8);  ROW_STEP(9);
    ROW_STEP(10); ROW_STEP(11); ROW_STEP(12); ROW_STEP(13); ROW_STEP(14);
    ROW_STEP(15); ROW_STEP(16); ROW_STEP(17); ROW_STEP(18); ROW_STEP(19);
    ROW_STEP(20);
}

extern "C" void kernel_launch(void* const* d_in, const int* in_sizes, int n_in,
                              void* d_out, int out_size)
{
    const float* x     = (const float*)d_in[0];
    const float* K_hit = (const float*)d_in[1];
    const float* K_mis = (const float*)d_in[2];
    float* out = (float*)d_out;

    dim3 grid(4, 6, OO * CC);     // 576 blocks, cap 4/SM -> balanced single wave
    dim3 block(32, 8);
    mnn_kernel<<<grid, block>>>(x, K_hit, K_mis, out);
}